// round 17
// baseline (speedup 1.0000x reference)
#include <cuda_runtime.h>
#include <cuda_fp16.h>
#include <cstdint>

// ---------------- problem constants ----------------
namespace {
constexpr int B    = 2;
constexpr int C0   = 64;
constexpr int C1   = 128;
constexpr int H    = 128, W = 128;
constexpr int HW   = H * W;            // 16384
constexpr int NPIX = B * HW;           // 32768
constexpr int R2   = 256;              // 16x16 reduced K/V
constexpr float BN_EPS = 1e-5f;
constexpr int WO_CONV1 = 0;
constexpr int WO_CONV2 = 73728;
constexpr int WO_SCONV = 221184;
constexpr int WO_TB    = 229376;
constexpr int WO_BLK   = 81920;
constexpr int W_TOTAL  = 393216;
}

// ---------------- scratch (static device, no allocs) ----------------
__device__ float g_pool[B * C0 * HW];
__device__ float g_t   [B * C1 * HW];
__device__ float g_o   [B * C1 * HW];
__device__ float g_qkv [B * C1 * HW];        // q only
__device__ __align__(16) __half g_uh[B * C1 * HW];   // fp16 dw3 output
__device__ __align__(16) unsigned g_apk[B * 64 * H * 130];  // paired fp16 act, padded
__device__ float g_ud  [B * C1 * R2];
__device__ __align__(16) unsigned g_kd16[B * 4 * 256 * 16]; // attn-ready packed K
__device__ __align__(16) unsigned g_vd16[B * 4 * 128 * 32]; // attn-ready packed V
__device__ __align__(16) __half g_wth[W_TOTAL];
__device__ double2 g_partP[64][128];         // pool stats partials
__device__ double2 g_partG[256][128];        // GEMM-epilogue stats partials [block][ch]
__device__ unsigned g_cntP = 0;
__device__ float g_A   [8 * 128];
__device__ float g_Bv  [8 * 128];

// ---------------- helpers ----------------
__device__ __forceinline__ void mma16(float c[4], const unsigned a[4], const unsigned b[2]) {
    asm volatile(
        "mma.sync.aligned.m16n8k16.row.col.f32.f16.f16.f32 "
        "{%0,%1,%2,%3},{%4,%5,%6,%7},{%8,%9},{%0,%1,%2,%3};"
        : "+f"(c[0]), "+f"(c[1]), "+f"(c[2]), "+f"(c[3])
        : "r"(a[0]), "r"(a[1]), "r"(a[2]), "r"(a[3]), "r"(b[0]), "r"(b[1]));
}
__device__ __forceinline__ void ldm4(unsigned a[4], const void* p) {
    unsigned addr = (unsigned)__cvta_generic_to_shared(p);
    asm volatile("ldmatrix.sync.aligned.m8n8.x4.shared.b16 {%0,%1,%2,%3}, [%4];"
        : "=r"(a[0]), "=r"(a[1]), "=r"(a[2]), "=r"(a[3]) : "r"(addr));
}
__device__ __forceinline__ void ldm4t(unsigned a[4], const void* p) {
    unsigned addr = (unsigned)__cvta_generic_to_shared(p);
    asm volatile("ldmatrix.sync.aligned.m8n8.x4.trans.shared.b16 {%0,%1,%2,%3}, [%4];"
        : "=r"(a[0]), "=r"(a[1]), "=r"(a[2]), "=r"(a[3]) : "r"(addr));
}
__device__ __forceinline__ void cpa16(void* dst, const void* src) {
    unsigned d = (unsigned)__cvta_generic_to_shared(dst);
    asm volatile("cp.async.ca.shared.global [%0], [%1], 16;" :: "r"(d), "l"(src));
}
__device__ __forceinline__ void cpa4(void* dst, const void* src) {
    unsigned d = (unsigned)__cvta_generic_to_shared(dst);
    asm volatile("cp.async.ca.shared.global [%0], [%1], 4;" :: "r"(d), "l"(src));
}
__device__ __forceinline__ unsigned h2u(__half2 h) {
    return *reinterpret_cast<unsigned*>(&h);
}
__device__ __forceinline__ unsigned packh2(float a, float b) {
    return h2u(__floats2half2_rn(a, b));
}

// ---------------- weight pre-convert fp32 -> fp16 (one launch) ----------------
struct WSeg { const float* src; int dst; int n; int cin; };
struct WArgs { WSeg s[9]; };
__global__ void k_wprep_all(WArgs a) {
    int i = (blockIdx.x * 256 + threadIdx.x) * 4;
#pragma unroll
    for (int t = 0; t < 9; t++) {
        if (i < a.s[t].n) {
            float v0, v1, v2, v3;
            if (a.s[t].cin == 0) {
                float4 v = *reinterpret_cast<const float4*>(a.s[t].src + i);
                v0 = v.x; v1 = v.y; v2 = v.z; v3 = v.w;
            } else {
                int cin = a.s[t].cin;
                int K = cin * 9;
                int co = i / K, r = i - co * K;
                int q = r / cin, ci = r - q * cin;
                const float* s = a.s[t].src + (size_t)co * K + ci * 9 + q;
                v0 = s[0]; v1 = s[9]; v2 = s[18]; v3 = s[27];
            }
            uint2 pk;
            pk.x = packh2(v0, v1);
            pk.y = packh2(v2, v3);
            *reinterpret_cast<uint2*>(g_wth + a.s[t].dst + i) = pk;
            return;
        }
        i -= a.s[t].n;
    }
}

// ---------------- maxpool 2x2 + fused dual-slot BN stats (slots 0, 2) ----------------
__global__ void k_maxpool(const float* __restrict__ x, float* __restrict__ out,
                          const float* __restrict__ gg1, const float* __restrict__ bb1,
                          const float* __restrict__ gg2, const float* __restrict__ bb2) {
    int tid = threadIdx.x;
    int i = blockIdx.x * 256 + tid;
    int p  = i & (HW - 1);
    int bc = i >> 14;
    int y = p >> 7, xx = p & 127;
    const float* ip = x + (size_t)bc * 65536 + (size_t)(y * 2) * 256 + xx * 2;
    float v = fmaxf(fmaxf(ip[0], ip[1]), fmaxf(ip[256], ip[257]));
    out[i] = v;
    // block covers one (bc, p>>8) slice: reduce sum/sq
    float s = v, q = v * v;
    int lane = tid & 31, wid = tid >> 5;
#pragma unroll
    for (int off = 16; off > 0; off >>= 1) {
        s += __shfl_down_sync(0xffffffffu, s, off);
        q += __shfl_down_sync(0xffffffffu, q, off);
    }
    __shared__ float ws[8], wq[8];
    __shared__ bool lastf;
    if (lane == 0) { ws[wid] = s; wq[wid] = q; }
    __syncthreads();
    if (tid == 0) {
        float S = 0.f, Q = 0.f;
#pragma unroll
        for (int w = 0; w < 8; w++) { S += ws[w]; Q += wq[w]; }
        int c = bc & 63, b = bc >> 6;
        int part = (b << 6) | (p >> 8);
        g_partP[c][part] = make_double2((double)S, (double)Q);
        __threadfence();
        unsigned vv = atomicAdd(&g_cntP, 1u);
        lastf = (vv == (unsigned)(gridDim.x - 1));
    }
    __syncthreads();
    if (lastf) {
        __threadfence();
        int cc = tid;
        if (cc < 64) {
            double S = 0., Q = 0.;
            for (int pp = 0; pp < 128; pp++) { S += g_partP[cc][pp].x; Q += g_partP[cc][pp].y; }
            double mean = S / (double)NPIX;
            double var  = Q / (double)NPIX - mean * mean;
            double rstd = 1.0 / sqrt(var + (double)BN_EPS);
            double A1 = (double)gg1[cc] * rstd;
            g_A[0 * 128 + cc]  = (float)A1;
            g_Bv[0 * 128 + cc] = (float)((double)bb1[cc] - mean * A1);
            double A2 = (double)gg2[cc] * rstd;
            g_A[2 * 128 + cc]  = (float)A2;
            g_Bv[2 * 128 + cc] = (float)((double)bb2[cc] - mean * A2);
        }
        if (tid == 0) g_cntP = 0;
    }
}

// ---------------- BN finalize from GEMM partials (1 block, 256 thr) ----------------
__global__ void k_bnfin2(const float* __restrict__ gg, const float* __restrict__ bb,
                         int slot) {
    int ch = threadIdx.x >> 1, h = threadIdx.x & 1;
    double S = 0., Q = 0.;
    int p0 = h * 128;
    for (int p = p0; p < p0 + 128; p++) {
        double2 v = g_partG[p][ch];
        S += v.x; Q += v.y;
    }
    __shared__ double sS[128], sQ[128];
    if (h == 1) { sS[ch] = S; sQ[ch] = Q; }
    __syncthreads();
    if (h == 0) {
        S += sS[ch]; Q += sQ[ch];
        double mean = S / (double)NPIX;
        double var  = Q / (double)NPIX - mean * mean;
        double rstd = 1.0 / sqrt(var + (double)BN_EPS);
        double A    = (double)gg[ch] * rstd;
        g_A[slot * 128 + ch]  = (float)A;
        g_Bv[slot * 128 + ch] = (float)((double)bb[ch] - mean * A);
    }
}

// ---------------- activation prep: BN+ReLU -> paired fp16, width-padded ----------------
__global__ void k_actprep(const float* __restrict__ x, int CP, int slot) {
    int i = blockIdx.x * 256 + threadIdx.x;
    int col = i & 127;
    int rest = i >> 7;
    int y = rest & 127;
    int bcp = rest >> 7;
    int cp = bcp % CP;
    int b = bcp / CP;
    const float* p0 = x + ((size_t)(b * 2 * CP) + 2 * cp) * HW + y * 128 + col;
    float v0 = p0[0], v1 = p0[HW];
    float A0 = g_A[slot * 128 + 2 * cp],     B0 = g_Bv[slot * 128 + 2 * cp];
    float A1 = g_A[slot * 128 + 2 * cp + 1], B1 = g_Bv[slot * 128 + 2 * cp + 1];
    v0 = fmaxf(fmaf(v0, A0, B0), 0.f);
    v1 = fmaxf(fmaf(v1, A1, B1), 0.f);
    unsigned* row = g_apk + (size_t)bcp * 128 * 130 + y * 130;
    row[col + 1] = packh2(v0, v1);
    if (col == 0)   row[0]   = 0u;
    if (col == 127) row[129] = 0u;
}

// ---------------- pipelined fp16 GEMM (CONV: im2col from apk; else flat fp16 in) ----------
template <int K, int CIN, bool CONV, bool ADD, bool STAT>
__global__ __launch_bounds__(256)
void k_pgemm(const __half* __restrict__ in, float* __restrict__ out,
             const float* __restrict__ add, int woff) {
    extern __shared__ __align__(16) unsigned char smraw[];
    constexpr int ABYTES = 128 * 40 * 2;     // 10240
    constexpr int BBYTES = 16 * 136 * 4;     // 8704
    constexpr int STAGE  = ABYTES + BBYTES;
    constexpr int CP = CIN / 2;
    constexpr int NC = K / 32;

    const int tid = threadIdx.x;
    const int lane = tid & 31, warp = tid >> 5;
    const int gid = lane >> 2, qid = lane & 3;
    const int wm = (warp & 1) * 64, wn = (warp >> 1) * 32;

    const int n0 = blockIdx.x * 128;
    const int b  = n0 >> 14;
    const int pbase = n0 & (HW - 1);
    const int y = pbase >> 7;

    const __half* wbase = g_wth + woff;
    const __half* inh = in + (size_t)b * CIN * HW;

    float c[4][4][4];
#pragma unroll
    for (int mt = 0; mt < 4; mt++)
#pragma unroll
        for (int nt = 0; nt < 4; nt++)
#pragma unroll
            for (int e = 0; e < 4; e++) c[mt][nt][e] = 0.f;

    const int a_row = tid >> 1;
    const int a_c   = (tid & 1) * 16;
    const int b_row = tid >> 4;
    const int b_col = (tid & 15) * 8;
    const int f_row = tid >> 3;
    const int f_col = (tid & 7) * 16;

    const int a_off = (wm + (lane & 15)) * 40 + ((lane >> 4) << 3);

    auto issue = [&](int ch) {
        unsigned char* base = smraw + (ch % 3) * STAGE;
        __half* dA = reinterpret_cast<__half*>(base);
        int k0 = ch * 32;
        const __half* srcA = wbase + (size_t)a_row * K + k0 + a_c;
        cpa16(dA + a_row * 40 + a_c, srcA);
        cpa16(dA + a_row * 40 + a_c + 8, srcA + 8);
        if (CONV) {
            unsigned* dB = reinterpret_cast<unsigned*>(base + ABYTES);
            int q   = k0 / CIN;
            int cb2 = (k0 - q * CIN) >> 1;
            int dyq = q / 3 - 1, dxq = q - (q / 3) * 3 - 1;
            int gy = y + dyq;
            unsigned* db = dB + b_row * 136 + b_col;
            if ((unsigned)gy < 128u) {
                const unsigned* src = g_apk
                    + ((size_t)(b * CP + cb2 + b_row) * 128 + gy) * 130 + b_col + dxq + 1;
#pragma unroll
                for (int e = 0; e < 8; e++) cpa4(db + e, src + e);
            } else {
#pragma unroll
                for (int e = 0; e < 8; e++) db[e] = 0u;
            }
        } else {
            __half* dB = reinterpret_cast<__half*>(base + ABYTES);
            const __half* src = inh + (size_t)(k0 + f_row) * HW + pbase + f_col;
            __half* dst = dB + f_row * 136 + f_col;
            cpa16(dst, src);
            cpa16(dst + 8, src + 8);
        }
        asm volatile("cp.async.commit_group;");
    };

    issue(0);
    if (NC > 1) issue(1);

    for (int ch = 0; ch < NC; ch++) {
        if (ch < NC - 1) asm volatile("cp.async.wait_group 1;");
        else             asm volatile("cp.async.wait_group 0;");
        __syncthreads();
        if (ch + 2 < NC) issue(ch + 2);

        unsigned char* base = smraw + (ch % 3) * STAGE;
        const __half* cA = reinterpret_cast<const __half*>(base);
#pragma unroll
        for (int ks = 0; ks < 2; ks++) {
            unsigned af[4][4], bf[4][2];
#pragma unroll
            for (int mt = 0; mt < 4; mt++)
                ldm4(af[mt], cA + a_off + mt * 16 * 40 + ks * 16);
            if (CONV) {
                const unsigned* cB = reinterpret_cast<const unsigned*>(base + ABYTES);
#pragma unroll
                for (int nt = 0; nt < 4; nt++) {
                    int n = wn + nt * 8 + gid;
                    bf[nt][0] = cB[(8 * ks + qid) * 136 + n];
                    bf[nt][1] = cB[(8 * ks + qid + 4) * 136 + n];
                }
            } else {
                const __half* basep = reinterpret_cast<const __half*>(base + ABYTES)
                    + (ks * 16 + (lane & 15)) * 136 + wn + ((lane >> 4) << 3);
                unsigned r[4];
                ldm4t(r, basep);
                bf[0][0] = r[0]; bf[0][1] = r[1];
                bf[1][0] = r[2]; bf[1][1] = r[3];
                ldm4t(r, basep + 16);
                bf[2][0] = r[0]; bf[2][1] = r[1];
                bf[3][0] = r[2]; bf[3][1] = r[3];
            }
#pragma unroll
            for (int mt = 0; mt < 4; mt++)
#pragma unroll
                for (int nt = 0; nt < 4; nt++)
                    mma16(c[mt][nt], af[mt], bf[nt]);
        }
    }

    float ss[4][2], sq[4][2];
    if (STAT) {
#pragma unroll
        for (int mt = 0; mt < 4; mt++) { ss[mt][0]=ss[mt][1]=sq[mt][0]=sq[mt][1]=0.f; }
    }
#pragma unroll
    for (int mt = 0; mt < 4; mt++) {
        int co = wm + mt * 16 + gid;
#pragma unroll
        for (int nt = 0; nt < 4; nt++) {
            int cb = wn + nt * 8 + qid * 2;
            size_t idx0 = ((size_t)(b * 128) + co) * HW + pbase + cb;
            size_t idx1 = ((size_t)(b * 128) + co + 8) * HW + pbase + cb;
            float2 r0 = make_float2(c[mt][nt][0], c[mt][nt][1]);
            float2 r1 = make_float2(c[mt][nt][2], c[mt][nt][3]);
            if (ADD) {
                float2 a0 = *reinterpret_cast<const float2*>(add + idx0);
                float2 a1 = *reinterpret_cast<const float2*>(add + idx1);
                r0.x += a0.x; r0.y += a0.y; r1.x += a1.x; r1.y += a1.y;
            }
            if (STAT) {
                ss[mt][0] += r0.x + r0.y;
                sq[mt][0] = fmaf(r0.x, r0.x, fmaf(r0.y, r0.y, sq[mt][0]));
                ss[mt][1] += r1.x + r1.y;
                sq[mt][1] = fmaf(r1.x, r1.x, fmaf(r1.y, r1.y, sq[mt][1]));
            }
            *reinterpret_cast<float2*>(out + idx0) = r0;
            *reinterpret_cast<float2*>(out + idx1) = r1;
        }
    }
    if (STAT) {
#pragma unroll
        for (int off = 1; off <= 2; off <<= 1) {
#pragma unroll
            for (int mt = 0; mt < 4; mt++) {
                ss[mt][0] += __shfl_xor_sync(0xffffffffu, ss[mt][0], off);
                ss[mt][1] += __shfl_xor_sync(0xffffffffu, ss[mt][1], off);
                sq[mt][0] += __shfl_xor_sync(0xffffffffu, sq[mt][0], off);
                sq[mt][1] += __shfl_xor_sync(0xffffffffu, sq[mt][1], off);
            }
        }
        __syncthreads();
        float* st = reinterpret_cast<float*>(smraw);   // [4 pairrow][128 ch][2]
        int prow = warp >> 1;
        if (qid == 0) {
#pragma unroll
            for (int mt = 0; mt < 4; mt++) {
                int c0 = wm + mt * 16 + gid;
                st[(prow * 128 + c0) * 2]     = ss[mt][0];
                st[(prow * 128 + c0) * 2 + 1] = sq[mt][0];
                st[(prow * 128 + c0 + 8) * 2]     = ss[mt][1];
                st[(prow * 128 + c0 + 8) * 2 + 1] = sq[mt][1];
            }
        }
        __syncthreads();
        if (tid < 128) {
            float S = 0.f, Q = 0.f;
#pragma unroll
            for (int r = 0; r < 4; r++) {
                S += st[(r * 128 + tid) * 2];
                Q += st[(r * 128 + tid) * 2 + 1];
            }
            g_partG[blockIdx.x][tid] = make_double2((double)S, (double)Q);
        }
    }
}

// ---------------- fp32-in GEMM with fused BN+ReLU, +add (sconv, mlp) ----------------
template <int K, bool STAT>
__global__ __launch_bounds__(256)
void k_gemm(const float* __restrict__ in, float* __restrict__ out,
            const float* __restrict__ add, int slot, int woff) {
    __shared__ __align__(16) __half sA[128 * 40];
    __shared__ __align__(16) __half sB[16 * 272];

    const int tid = threadIdx.x;
    const int lane = tid & 31, warp = tid >> 5;
    const int gid = lane >> 2, qid = lane & 3;
    const int wm = (warp & 1) * 64, wn = (warp >> 1) * 32;

    const int n0 = blockIdx.x * 128;
    const int b  = n0 >> 14;
    const int pbase = n0 & (HW - 1);

    const float* Ap = g_A  + slot * 128;
    const float* Bp = g_Bv + slot * 128;
    const __half* wbase = g_wth + woff;
    const float* inb = in + (size_t)b * K * HW;

    float c[4][4][4];
#pragma unroll
    for (int mt = 0; mt < 4; mt++)
#pragma unroll
        for (int nt = 0; nt < 4; nt++)
#pragma unroll
            for (int e = 0; e < 4; e++) c[mt][nt][e] = 0.f;

    const int a_row = tid >> 1;
    const int a_c   = (tid & 1) * 16;
    const int colg  = tid & 31;
    const int kp    = tid >> 5;

    __half* a_ld = sA + (wm + (lane & 15)) * 40 + ((lane >> 4) << 3);
    const unsigned* sbw = reinterpret_cast<const unsigned*>(sB);

    for (int k0 = 0; k0 < K; k0 += 32) {
        __syncthreads();
        {
            const __half* src = wbase + (size_t)a_row * K + k0 + a_c;
            __half* dst = sA + a_row * 40 + a_c;
            cpa16(dst, src);
            cpa16(dst + 8, src + 8);
        }
        asm volatile("cp.async.commit_group;");
#pragma unroll
        for (int it = 0; it < 2; it++) {
            int kpair = kp + it * 8;
            int ke = k0 + kpair * 2;
            float ve[4], vo[4];
#pragma unroll
            for (int half = 0; half < 2; half++) {
                int k = ke + half;
                float* v = half ? vo : ve;
                float4 xv = *reinterpret_cast<const float4*>(
                    inb + (size_t)k * HW + pbase + colg * 4);
                float A = Ap[k], Bb = Bp[k];
                v[0] = fmaxf(fmaf(xv.x, A, Bb), 0.f);
                v[1] = fmaxf(fmaf(xv.y, A, Bb), 0.f);
                v[2] = fmaxf(fmaf(xv.z, A, Bb), 0.f);
                v[3] = fmaxf(fmaf(xv.w, A, Bb), 0.f);
            }
            uint4 pk;
            pk.x = packh2(ve[0], vo[0]);
            pk.y = packh2(ve[1], vo[1]);
            pk.z = packh2(ve[2], vo[2]);
            pk.w = packh2(ve[3], vo[3]);
            *reinterpret_cast<uint4*>(sB + kpair * 272 + colg * 8) = pk;
        }
        asm volatile("cp.async.wait_group 0;");
        __syncthreads();
#pragma unroll
        for (int ks = 0; ks < 2; ks++) {
            unsigned af[4][4], bf[4][2];
#pragma unroll
            for (int mt = 0; mt < 4; mt++)
                ldm4(af[mt], a_ld + mt * 16 * 40 + ks * 16);
#pragma unroll
            for (int nt = 0; nt < 4; nt++) {
                int n = wn + nt * 8 + gid;
                bf[nt][0] = sbw[(8 * ks + qid) * 136 + n];
                bf[nt][1] = sbw[(8 * ks + qid + 4) * 136 + n];
            }
#pragma unroll
            for (int mt = 0; mt < 4; mt++)
#pragma unroll
                for (int nt = 0; nt < 4; nt++)
                    mma16(c[mt][nt], af[mt], bf[nt]);
        }
    }

    float ss[4][2], sq[4][2];
    if (STAT) {
#pragma unroll
        for (int mt = 0; mt < 4; mt++) { ss[mt][0]=ss[mt][1]=sq[mt][0]=sq[mt][1]=0.f; }
    }
#pragma unroll
    for (int mt = 0; mt < 4; mt++) {
        int co = wm + mt * 16 + gid;
#pragma unroll
        for (int nt = 0; nt < 4; nt++) {
            int cb = wn + nt * 8 + qid * 2;
            size_t idx0 = ((size_t)(b * 128) + co) * HW + pbase + cb;
            size_t idx1 = ((size_t)(b * 128) + co + 8) * HW + pbase + cb;
            float2 a0 = *reinterpret_cast<const float2*>(add + idx0);
            float2 a1 = *reinterpret_cast<const float2*>(add + idx1);
            float2 r0 = make_float2(c[mt][nt][0] + a0.x, c[mt][nt][1] + a0.y);
            float2 r1 = make_float2(c[mt][nt][2] + a1.x, c[mt][nt][3] + a1.y);
            if (STAT) {
                ss[mt][0] += r0.x + r0.y;
                sq[mt][0] = fmaf(r0.x, r0.x, fmaf(r0.y, r0.y, sq[mt][0]));
                ss[mt][1] += r1.x + r1.y;
                sq[mt][1] = fmaf(r1.x, r1.x, fmaf(r1.y, r1.y, sq[mt][1]));
            }
            *reinterpret_cast<float2*>(out + idx0) = r0;
            *reinterpret_cast<float2*>(out + idx1) = r1;
        }
    }
    if (STAT) {
#pragma unroll
        for (int off = 1; off <= 2; off <<= 1) {
#pragma unroll
            for (int mt = 0; mt < 4; mt++) {
                ss[mt][0] += __shfl_xor_sync(0xffffffffu, ss[mt][0], off);
                ss[mt][1] += __shfl_xor_sync(0xffffffffu, ss[mt][1], off);
                sq[mt][0] += __shfl_xor_sync(0xffffffffu, sq[mt][0], off);
                sq[mt][1] += __shfl_xor_sync(0xffffffffu, sq[mt][1], off);
            }
        }
        __syncthreads();
        float* st = reinterpret_cast<float*>(sA);   // reuse: [4][128][2]
        int prow = warp >> 1;
        if (qid == 0) {
#pragma unroll
            for (int mt = 0; mt < 4; mt++) {
                int c0 = wm + mt * 16 + gid;
                st[(prow * 128 + c0) * 2]     = ss[mt][0];
                st[(prow * 128 + c0) * 2 + 1] = sq[mt][0];
                st[(prow * 128 + c0 + 8) * 2]     = ss[mt][1];
                st[(prow * 128 + c0 + 8) * 2 + 1] = sq[mt][1];
            }
        }
        __syncthreads();
        if (tid < 128) {
            float S = 0.f, Q = 0.f;
#pragma unroll
            for (int r = 0; r < 4; r++) {
                S += st[(r * 128 + tid) * 2];
                Q += st[(r * 128 + tid) * 2 + 1];
            }
            g_partG[blockIdx.x][tid] = make_double2((double)S, (double)Q);
        }
    }
}

// ---------------- depthwise 3x3 -> fp16 out ----------------
template <int BN>
__global__ void k_dw3(const float* __restrict__ in, const float* __restrict__ w,
                      __half* __restrict__ out, int slot) {
    int i = blockIdx.x * 256 + threadIdx.x;
    int idx = i * 4;
    int p  = idx & (HW - 1);
    int bc = idx >> 14;
    int c  = bc & 127;
    int y = p >> 7, x0 = p & 127;
    const float* ip = in + (size_t)bc * HW;
    const float* wp = w + c * 9;
    float A = 1.f, Bb = 0.f;
    if (BN) { A = g_A[slot * 128 + c]; Bb = g_Bv[slot * 128 + c]; }
    float acc[4] = {0.f, 0.f, 0.f, 0.f};
#pragma unroll
    for (int dy = 0; dy < 3; dy++) {
        int gy = y + dy - 1;
        if ((unsigned)gy >= 128u) continue;
        const float* r = ip + gy * 128;
        float4 m = *reinterpret_cast<const float4*>(r + x0);
        float v[6];
        v[0] = (x0 > 0)   ? r[x0 - 1] : 0.f;
        v[1] = m.x; v[2] = m.y; v[3] = m.z; v[4] = m.w;
        v[5] = (x0 < 124) ? r[x0 + 4] : 0.f;
        if (BN) {
            if (x0 > 0)   v[0] = fmaf(v[0], A, Bb);
            v[1] = fmaf(v[1], A, Bb); v[2] = fmaf(v[2], A, Bb);
            v[3] = fmaf(v[3], A, Bb); v[4] = fmaf(v[4], A, Bb);
            if (x0 < 124) v[5] = fmaf(v[5], A, Bb);
        }
        float w0 = wp[dy * 3], w1 = wp[dy * 3 + 1], w2 = wp[dy * 3 + 2];
#pragma unroll
        for (int e = 0; e < 4; e++)
            acc[e] = fmaf(v[e], w0, fmaf(v[e + 1], w1, fmaf(v[e + 2], w2, acc[e])));
    }
    uint2 pk;
    pk.x = packh2(acc[0], acc[1]);
    pk.y = packh2(acc[2], acc[3]);
    *reinterpret_cast<uint2*>(out + idx) = pk;
}

// ---------------- bilinear downsample of fp16 u ----------------
__global__ void k_ds2(const __half* __restrict__ u) {
    int i = blockIdx.x * 256 + threadIdx.x;
    int j  = i & 255;
    int c  = (i >> 8) & 127;
    int b  = i >> 15;
    const __half* ip = u + ((size_t)(b * C1) + c) * HW;
    int r = j >> 4, s = j & 15;
    const float step = (float)(127.0 / 15.0);
    float ph = (float)r * step;
    int   lh = min((int)ph, 126);
    float fh = ph - (float)lh;
    float pw = (float)s * step;
    int   lw = min((int)pw, 126);
    float fw = pw - (float)lw;
    const __half* p0 = ip + lh * 128 + lw;
    float v00 = __half2float(p0[0]),   v01 = __half2float(p0[1]);
    float v10 = __half2float(p0[128]), v11 = __half2float(p0[129]);
    g_ud[i] = (1.f - fh) * ((1.f - fw) * v00 + fw * v01)
            +        fh  * ((1.f - fw) * v10 + fw * v11);
}

// ---------------- kd/vd = W_kv @ ud, written attn-ready (packed fp16) ----------------
__global__ void k_kv(const float* __restrict__ w) {
    int og = blockIdx.x, b = blockIdx.y;
    int j = threadIdx.x;
    __shared__ float sw[16 * 128];
    for (int i = j; i < 16 * 128; i += 256)
        sw[i] = w[(size_t)(128 + og * 16) * 128 + i];
    __syncthreads();
    float acc[16];
#pragma unroll
    for (int r = 0; r < 16; r++) acc[r] = 0.f;
    const float* udb = g_ud + (size_t)b * C1 * R2 + j;
#pragma unroll 4
    for (int c = 0; c < 128; c++) {
        float v = udb[(size_t)c * R2];
#pragma unroll
        for (int r = 0; r < 16; r++) acc[r] = fmaf(sw[r * 128 + c], v, acc[r]);
    }
    if (og < 8) {
#pragma unroll
        for (int head = 0; head < 4; head++) {
            size_t base = ((size_t)(b * 4 + head) * 256 + j) * 16;
            g_kd16[base + 2 * og]     = packh2(acc[head],     acc[head + 4]);
            g_kd16[base + 2 * og + 1] = packh2(acc[8 + head], acc[12 + head]);
        }
    } else {
        int ogv = og - 8;
#pragma unroll
        for (int r = 0; r < 16; r++) {
            float partner = __shfl_down_sync(0xffffffffu, acc[r], 1);
            if ((j & 1) == 0) {
                int d = ogv * 4 + (r >> 2), head = r & 3;
                g_vd16[((size_t)(b * 4 + head) * 128 + (j >> 1)) * 32 + d] =
                    packh2(acc[r], partner);
            }
        }
    }
}

// ---------------- fp16 tensor-core attention (coalesced K/V staging) ----------------
__global__ __launch_bounds__(128)
void k_attn(const float* __restrict__ qbuf, const float* __restrict__ table,
            float* __restrict__ outp) {
    extern __shared__ unsigned smu[];
    unsigned* k16 = smu;                      // [256 j][20]
    unsigned* v16 = smu + 256 * 20;           // [128 jp][40]
    unsigned* q16 = v16 + 128 * 40;           // [64 r][20]
    float*    t_s = reinterpret_cast<float*>(q16 + 64 * 20);

    const int tid  = threadIdx.x;
    const int lane = tid & 31, warp = tid >> 5;
    const int gid  = lane >> 2, qid = lane & 3;
    const int bh   = blockIdx.y;
    const int b = bh >> 2, head = bh & 3;
    const int px0 = blockIdx.x * 64;
    const float scale = 0.17677669529663687f;
    const float PSC = 0.0625f;

    const uint4* kg = reinterpret_cast<const uint4*>(g_kd16) + (size_t)(b * 4 + head) * 1024;
    for (int i = tid; i < 1024; i += 128) {
        uint4 wv = kg[i];
        int j = i >> 2, c4 = (i & 3) << 2;
        *reinterpret_cast<uint4*>(k16 + j * 20 + c4) = wv;
    }
    const uint4* vg = reinterpret_cast<const uint4*>(g_vd16) + (size_t)(b * 4 + head) * 1024;
    for (int i = tid; i < 1024; i += 128) {
        uint4 wv = vg[i];
        int jp = i >> 3, c4 = (i & 7) << 2;
        *reinterpret_cast<uint4*>(v16 + jp * 40 + c4) = wv;
    }
    for (int i = tid; i < 16 * 64; i += 128) {
        int dp = i >> 6, r = i & 63;
        const float* base = qbuf + (size_t)b * C1 * HW + px0 + r;
        float a = base[(size_t)((2 * dp) * 4 + head) * HW] * scale;
        float bb2 = base[(size_t)((2 * dp + 1) * 4 + head) * HW] * scale;
        q16[r * 20 + dp] = packh2(a, bb2);
    }
    for (int i = tid; i < 961; i += 128) t_s[i] = table[i * 4 + head] * scale;
    __syncthreads();

    unsigned aq[2][4];
#pragma unroll
    for (int kc = 0; kc < 2; kc++) {
        const unsigned* r0 = q16 + (warp * 16 + gid) * 20 + kc * 8;
        const unsigned* r1 = r0 + 8 * 20;
        aq[kc][0] = r0[qid];
        aq[kc][1] = r1[qid];
        aq[kc][2] = r0[qid + 4];
        aq[kc][3] = r1[qid + 4];
    }
    float s[32][4];
#pragma unroll
    for (int nt = 0; nt < 32; nt++) { s[nt][0]=s[nt][1]=s[nt][2]=s[nt][3]=0.f; }
#pragma unroll
    for (int nt = 0; nt < 32; nt++) {
        const unsigned* kb = k16 + (nt * 8 + gid) * 20;
#pragma unroll
        for (int kc = 0; kc < 2; kc++) {
            unsigned bf[2];
            bf[0] = kb[kc * 8 + qid];
            bf[1] = kb[kc * 8 + qid + 4];
            mma16(s[nt], aq[kc], bf);
        }
    }

    const int xb = (px0 & 127) + warp * 16;
    const int rh = (px0 >> 7) >> 3;
    const int base0 = (rh + 15) * 31 + ((xb + gid) >> 3) + 15;
    const int base1 = (rh + 15) * 31 + ((xb + gid + 8) >> 3) + 15;
    float l0 = 0.f, l1 = 0.f;
#pragma unroll
    for (int nt = 0; nt < 32; nt++) {
        int j = nt * 8 + 2 * qid;
        int off = (j >> 4) * 31 + (j & 15);
        float e0 = __expf(s[nt][0] + t_s[base0 - off]);
        float e1 = __expf(s[nt][1] + t_s[base0 - off - 1]);
        float e2 = __expf(s[nt][2] + t_s[base1 - off]);
        float e3 = __expf(s[nt][3] + t_s[base1 - off - 1]);
        s[nt][0] = e0 * PSC; s[nt][1] = e1 * PSC;
        s[nt][2] = e2 * PSC; s[nt][3] = e3 * PSC;
        l0 += e0 + e1; l1 += e2 + e3;
    }
    l0 += __shfl_xor_sync(0xffffffffu, l0, 1);
    l0 += __shfl_xor_sync(0xffffffffu, l0, 2);
    l1 += __shfl_xor_sync(0xffffffffu, l1, 1);
    l1 += __shfl_xor_sync(0xffffffffu, l1, 2);
    const float inv0 = 1.f / (l0 * PSC), inv1 = 1.f / (l1 * PSC);

    float o[4][4];
#pragma unroll
    for (int nt = 0; nt < 4; nt++) { o[nt][0]=o[nt][1]=o[nt][2]=o[nt][3]=0.f; }
#pragma unroll
    for (int kc = 0; kc < 16; kc++) {
        unsigned a[4];
        a[0] = packh2(s[2 * kc][0],     s[2 * kc][1]);
        a[1] = packh2(s[2 * kc][2],     s[2 * kc][3]);
        a[2] = packh2(s[2 * kc + 1][0], s[2 * kc + 1][1]);
        a[3] = packh2(s[2 * kc + 1][2], s[2 * kc + 1][3]);
        const unsigned* vb0 = v16 + (kc * 8 + qid) * 40;
        const unsigned* vb1 = v16 + (kc * 8 + qid + 4) * 40;
#pragma unroll
        for (int ntd = 0; ntd < 4; ntd++) {
            unsigned bf[2];
            bf[0] = vb0[ntd * 8 + gid];
            bf[1] = vb1[ntd * 8 + gid];
            mma16(o[ntd], a, bf);
        }
    }

    const int px = px0 + warp * 16 + gid;
#pragma unroll
    for (int ntd = 0; ntd < 4; ntd++) {
        int d = ntd * 8 + 2 * qid;
        size_t c0 = ((size_t)(b * C1) + d * 4 + head) * HW;
        size_t c1 = ((size_t)(b * C1) + (d + 1) * 4 + head) * HW;
        outp[c0 + px]     = o[ntd][0] * inv0;
        outp[c1 + px]     = o[ntd][1] * inv0;
        outp[c0 + px + 8] = o[ntd][2] * inv1;
        outp[c1 + px + 8] = o[ntd][3] * inv1;
    }
}

// ---------------- host orchestration ----------------
extern "C" void kernel_launch(void* const* d_in, const int* in_sizes, int n_in,
                              void* d_out, int out_size) {
    (void)in_sizes; (void)n_in; (void)out_size;
    const float* x        = (const float*)d_in[0];
    const float* bb_bn1_g = (const float*)d_in[1];
    const float* bb_bn1_b = (const float*)d_in[2];
    const float* bb_conv1 = (const float*)d_in[3];
    const float* bb_bn2_g = (const float*)d_in[4];
    const float* bb_bn2_b = (const float*)d_in[5];
    const float* bb_conv2 = (const float*)d_in[6];
    const float* bb_sbn_g = (const float*)d_in[7];
    const float* bb_sbn_b = (const float*)d_in[8];
    const float* bb_sconv = (const float*)d_in[9];
    const float* tb_bn1_g = (const float*)d_in[10];
    const float* tb_bn1_b = (const float*)d_in[11];
    const float* tb_dwqkv = (const float*)d_in[12];
    const float* tb_pwqkv = (const float*)d_in[13];
    const float* tb_dwout = (const float*)d_in[14];
    const float* tb_pwout = (const float*)d_in[15];
    const float* tb_rel   = (const float*)d_in[16];
    const float* tb_bn2_g = (const float*)d_in[17];
    const float* tb_bn2_b = (const float*)d_in[18];
    const float* tb_mlp   = (const float*)d_in[19];

    void* pv;
    float *pool, *t, *o, *qb;
    __half* uh;
    cudaGetSymbolAddress(&pv, g_pool); pool = (float*)pv;
    cudaGetSymbolAddress(&pv, g_t);    t    = (float*)pv;
    cudaGetSymbolAddress(&pv, g_o);    o    = (float*)pv;
    cudaGetSymbolAddress(&pv, g_qkv);  qb   = (float*)pv;
    cudaGetSymbolAddress(&pv, g_uh);   uh   = (__half*)pv;

    const int ATTN_SMEM = (256 * 20 + 128 * 40 + 64 * 20) * 4 + 961 * 4;
    cudaFuncSetAttribute(k_attn, cudaFuncAttributeMaxDynamicSharedMemorySize, ATTN_SMEM);
    const int CG_SMEM = 3 * (128 * 40 * 2 + 16 * 136 * 4);   // 56832
    cudaFuncSetAttribute(k_pgemm<576, 64, true, false, true>,
                         cudaFuncAttributeMaxDynamicSharedMemorySize, CG_SMEM);
    cudaFuncSetAttribute(k_pgemm<1152, 128, true, false, false>,
                         cudaFuncAttributeMaxDynamicSharedMemorySize, CG_SMEM);
    cudaFuncSetAttribute(k_pgemm<128, 128, false, false, false>,
                         cudaFuncAttributeMaxDynamicSharedMemorySize, CG_SMEM);
    cudaFuncSetAttribute(k_pgemm<128, 128, false, true, true>,
                         cudaFuncAttributeMaxDynamicSharedMemorySize, CG_SMEM);

    const dim3 g1(NPIX / 128, 1);
    const dim3 ga(HW / 64, B * 4);

    WArgs wa;
    wa.s[0] = { bb_conv1, WO_CONV1, 128 * 576,  64 };
    wa.s[1] = { bb_conv2, WO_CONV2, 128 * 1152, 128 };
    wa.s[2] = { bb_sconv, WO_SCONV, 128 * 64,   0 };
    wa.s[3] = { tb_pwqkv,               WO_TB,                       384 * 128, 0 };
    wa.s[4] = { tb_pwout,               WO_TB + 49152,               128 * 128, 0 };
    wa.s[5] = { tb_mlp,                 WO_TB + 65536,               128 * 128, 0 };
    wa.s[6] = { tb_pwqkv + 384 * 128,   WO_TB + WO_BLK,              384 * 128, 0 };
    wa.s[7] = { tb_pwout + 128 * 128,   WO_TB + WO_BLK + 49152,      128 * 128, 0 };
    wa.s[8] = { tb_mlp + 128 * 128,     WO_TB + WO_BLK + 65536,      128 * 128, 0 };
    k_wprep_all<<<W_TOTAL / 1024, 256>>>(wa);

    // maxpool + fused pool stats (slots 0 and 2)
    k_maxpool<<<(B * C0 * HW) / 256, 256>>>(x, pool, bb_bn1_g, bb_bn1_b, bb_sbn_g, bb_sbn_b);

    // ---- BasicBlock ----
    k_actprep<<<(B * 32 * HW) / 256, 256>>>(pool, 32, 0);
    k_pgemm<576, 64, true, false, true><<<g1, 256, CG_SMEM>>>(nullptr, t, nullptr, WO_CONV1);
    k_bnfin2<<<1, 256>>>(bb_bn2_g, bb_bn2_b, 1);
    k_actprep<<<(B * 64 * HW) / 256, 256>>>(t, 64, 1);
    k_pgemm<1152, 128, true, false, false><<<g1, 256, CG_SMEM>>>(nullptr, o, nullptr, WO_CONV2);
    k_gemm<64, true><<<g1, 256>>>(pool, o, o, 2, WO_SCONV);          // o += sconv; stats
    k_bnfin2<<<1, 256>>>(tb_bn1_g, tb_bn1_b, 3);

    // ---- 2 x BasicTransBlock (ping-pong residual between o and t) ----
    float* ob = o;
    float* tb = t;
    for (int i = 0; i < 2; i++) {
        const int wo = WO_TB + i * WO_BLK;
        k_dw3<1><<<(B * C1 * HW) / 1024, 256>>>(ob, tb_dwqkv + (size_t)i * 128 * 9, uh, 3);
        k_pgemm<128, 128, false, false, false><<<g1, 256, CG_SMEM>>>(uh, qb, nullptr, wo);
        k_ds2<<<(B * C1 * R2) / 256, 256>>>(uh);
        k_kv<<<dim3(16, B), 256>>>(tb_pwqkv + (size_t)i * 384 * 128);
        k_attn<<<ga, 128, ATTN_SMEM>>>(qb, tb_rel + (size_t)i * 961 * 4, tb);
        k_dw3<0><<<(B * C1 * HW) / 1024, 256>>>(tb, tb_dwout + (size_t)i * 128 * 9, uh, 0);
        k_pgemm<128, 128, false, true, true><<<g1, 256, CG_SMEM>>>(uh, ob, ob, wo + 49152);
        k_bnfin2<<<1, 256>>>(tb_bn2_g + i * 128, tb_bn2_b + i * 128, 4);
        float* dest = (i == 1) ? (float*)d_out : tb;
        if (i == 0) {
            k_gemm<128, true><<<g1, 256>>>(ob, dest, ob, 4, wo + 65536);
            k_bnfin2<<<1, 256>>>(tb_bn1_g + 128, tb_bn1_b + 128, 3);
        } else {
            k_gemm<128, false><<<g1, 256>>>(ob, dest, ob, 4, wo + 65536);
        }
        float* tmp = ob; ob = tb; tb = tmp;
    }
}